// round 12
// baseline (speedup 1.0000x reference)
#include <cuda_runtime.h>
#include <cstdint>

#define TLEN 4096
#define NH 32
#define HS 64
#define DIM (NH*HS)
#define NSLOT 16
#define STRIDE 336   // floats/slot: w64|k64|a64|b64|r64|v16

// grid=128 (32 heads x 4 quarters of 16 rows), block=128 = 4 warps.
// Warp ww computes 4 rows [q*16+ww*4, +4): 2 groups x 8 lanes, each lane
// owns TWO rows' 8-float j-slice (f32x2). Lanes 16-31 mirror lanes 0-15
// (same rows; LDS broadcasts, shfl butterflies stay uniform; stores guarded).
// ONE shared cp.async ring (16 slots, 14-step lookahead), filled by 84 x 16B
// chunks (chunk = tid), one __syncthreads per PAIR of steps.

__device__ __forceinline__ uint32_t smem_u32(const void* p) {
    return (uint32_t)__cvta_generic_to_shared(p);
}

typedef unsigned long long u64;

#define MUL2(d,a,b)   asm("mul.rn.f32x2 %0, %1, %2;"     : "=l"(d) : "l"(a), "l"(b))
#define FMA2(d,a,b,c) asm("fma.rn.f32x2 %0, %1, %2, %3;" : "=l"(d) : "l"(a), "l"(b), "l"(c))
#define PACK2(d,lo,hi)   asm("mov.b64 %0, {%1, %2};" : "=l"(d) : "f"(lo), "f"(hi))
#define UNPACK2(lo,hi,v) asm("mov.b64 {%0, %1}, %2;" : "=f"(lo), "=f"(hi) : "l"(v))

#define DOT8(res, X, Y) do { \
    u64 _p; MUL2(_p, X[0], Y[0]); FMA2(_p, X[1], Y[1], _p); \
    FMA2(_p, X[2], Y[2], _p);     FMA2(_p, X[3], Y[3], _p); \
    float _lo, _hi; UNPACK2(_lo, _hi, _p); res = _lo + _hi; } while(0)

#define RED8(x) do { \
    x += __shfl_xor_sync(0xffffffffu, x, 1); \
    x += __shfl_xor_sync(0xffffffffu, x, 2); \
    x += __shfl_xor_sync(0xffffffffu, x, 4); } while(0)

#define LD4x2(dst, ptr) do { \
    const ulonglong2* _p = (const ulonglong2*)(ptr); \
    ulonglong2 _x0 = _p[0], _x1 = _p[1]; \
    dst[0]=_x0.x; dst[1]=_x0.y; dst[2]=_x1.x; dst[3]=_x1.y; } while(0)

__global__ void __launch_bounds__(128, 1) wkv7_kernel(
    const float* __restrict__ rr, const float* __restrict__ ww,
    const float* __restrict__ kk, const float* __restrict__ vv_,
    const float* __restrict__ aa, const float* __restrict__ bb,
    const float* __restrict__ s0, float* __restrict__ y, float* __restrict__ sout)
{
    const int blk   = blockIdx.x;
    const int h     = blk >> 2;
    const int q     = blk & 3;
    const int tid   = threadIdx.x;
    const int warp  = tid >> 5;
    const int lane  = tid & 31;
    const int lane8 = lane & 7;
    const int g2    = (lane >> 3) & 1;       // group (mirrored for lanes 16+)
    const int j0    = lane8 * 8;
    const int hbase = h * HS;
    const int rloc  = warp * 4 + g2 * 2;     // 0..15 (rows rloc, rloc+1)
    const int row   = q * 16 + rloc;
    const bool st_ok = (lane < 16);          // only real lanes store

    __shared__ __align__(16) float ring[NSLOT][STRIDE];

    u64 sA[4], sB[4];
    {
        const float* sp = s0 + ((size_t)h * HS + row) * HS + j0;
        LD4x2(sA, sp);
        LD4x2(sB, sp + HS);
    }

    // Cooperative fill: chunk c = tid (c<84), one 16B cp.async per slot.
    const float* gsrc = 0; uint32_t od = 0;
    {
        int c = tid;
        if (c < 80) {
            int f   = c >> 4;
            int ofs = (c & 15) * 4;
            const float* fp = (f == 0) ? ww : (f == 1) ? kk : (f == 2) ? aa
                            : (f == 3) ? bb : rr;
            gsrc = fp + hbase + ofs;
            od   = f * 64 + ofs;
        } else if (c < 84) {
            gsrc = vv_ + hbase + q * 16 + (c - 80) * 4;
            od   = 320 + (c - 80) * 4;
        }
    }

#define ISSUEP(T0, SA_, SB_) do { \
    if (gsrc) { \
        asm volatile("cp.async.cg.shared.global [%0], [%1], 16;" \
            :: "r"(smem_u32(&ring[(SA_)][0]) + od * 4u), "l"(gsrc + (size_t)(T0) * DIM)); \
        asm volatile("cp.async.cg.shared.global [%0], [%1], 16;" \
            :: "r"(smem_u32(&ring[(SB_)][0]) + od * 4u), "l"(gsrc + (size_t)((T0) + 1) * DIM)); \
    } \
    asm volatile("cp.async.commit_group;"); \
} while(0)

    // Prologue: 7 commits covering times/slots 0..13
    #pragma unroll
    for (int n = 0; n < 7; n++) ISSUEP(2 * n, 2 * n, 2 * n + 1);

    asm volatile("cp.async.wait_group 5;");
    __syncthreads();

    u64 a2[4];                       // a_t for the coming step
    LD4x2(a2, &ring[0][128 + j0]);

    float yv0 = 0.f, yv1 = 0.f;
    float* const ybase = y + hbase + row;

// Step body. SLOT = slot of t; SLOTN = slot of t+1 (a-prefetch).
#define STEPBODY(T, SLOT, SLOTN) do { \
    const float* sl  = &ring[SLOT][0]; \
    const float* sln = &ring[SLOTN][0]; \
    float sa0, sa1; \
    DOT8(sa0, sA, a2); \
    DOT8(sa1, sB, a2); \
    RED8(sa0); \
    RED8(sa1); \
    { \
        float u0 = yv0, u1 = yv1; \
        RED8(u0); \
        RED8(u1); \
        int tprev = (T) - ((T) != 0); \
        if (st_ok && lane8 == 0) \
            *(float2*)&ybase[(size_t)tprev * DIM] = make_float2(u0, u1); \
    } \
    u64 w2[4], k2[4], b2[4], r2[4]; \
    LD4x2(w2, sl + j0); \
    LD4x2(k2, sl + 64 + j0); \
    LD4x2(b2, sl + 192 + j0); \
    LD4x2(r2, sl + 256 + j0); \
    const float2 vpair = *(const float2*)(sl + 320 + rloc); \
    LD4x2(a2, sln + 128 + j0); \
    u64 v0b, v1b, sa0b, sa1b; \
    PACK2(v0b, vpair.x, vpair.x); PACK2(v1b, vpair.y, vpair.y); \
    PACK2(sa0b, sa0, sa0);        PACK2(sa1b, sa1, sa1); \
    _Pragma("unroll") \
    for (int i = 0; i < 4; i++) { \
        u64 t0; MUL2(t0, sA[i], w2[i]); \
        FMA2(t0, v0b, k2[i], t0); \
        FMA2(sA[i], sa0b, b2[i], t0); \
        u64 t1; MUL2(t1, sB[i], w2[i]); \
        FMA2(t1, v1b, k2[i], t1); \
        FMA2(sB[i], sa1b, b2[i], t1); \
    } \
    u64 yp0, yp1; \
    MUL2(yp0, sA[0], r2[0]); FMA2(yp0, sA[1], r2[1], yp0); \
    FMA2(yp0, sA[2], r2[2], yp0); FMA2(yp0, sA[3], r2[3], yp0); \
    MUL2(yp1, sB[0], r2[0]); FMA2(yp1, sB[1], r2[1], yp1); \
    FMA2(yp1, sB[2], r2[2], yp1); FMA2(yp1, sB[3], r2[3], yp1); \
    { \
        float l0, h0, l1, h1; \
        UNPACK2(l0, h0, yp0); UNPACK2(l1, h1, yp1); \
        yv0 = l0 + h0; yv1 = l1 + h1; \
    } \
} while(0)

    // Main: 8 pairs per 16-step block; one wait+bar per pair.
    for (int tb = 0; tb < TLEN - NSLOT; tb += NSLOT) {
        #pragma unroll
        for (int pu = 0; pu < 8; pu++) {
            const int t = tb + 2 * pu;
            asm volatile("cp.async.wait_group 5;");
            __syncthreads();
            STEPBODY(t,     2 * pu,            2 * pu + 1);
            STEPBODY(t + 1, 2 * pu + 1,       (2 * pu + 2) & 15);
            ISSUEP(t + 14, (2 * pu + 14) & 15, (2 * pu + 15) & 15);
        }
    }

    // Tail: issue last pair (4094,4095), drain, then 8 bar-free pairs.
    __syncthreads();
    ISSUEP(TLEN - 2, 14, 15);
    asm volatile("cp.async.wait_group 0;");
    __syncthreads();
    #pragma unroll
    for (int pu = 0; pu < 8; pu++) {
        const int t = TLEN - NSLOT + 2 * pu;
        STEPBODY(t,     2 * pu,            2 * pu + 1);
        STEPBODY(t + 1, 2 * pu + 1,       (2 * pu + 2) & 15);  // last a2 unused
    }

    // Epilogue: y_{TLEN-1}
    {
        RED8(yv0);
        RED8(yv1);
        if (st_ok && lane8 == 0)
            *(float2*)&ybase[(size_t)(TLEN - 1) * DIM] = make_float2(yv0, yv1);
    }

    // Final state (guarded: mirrored lanes must not store)
    if (st_ok) {
        float* sp = sout + ((size_t)h * HS + row) * HS + j0;
        ulonglong2* p0 = (ulonglong2*)sp;
        ulonglong2* p1 = (ulonglong2*)(sp + HS);
        ulonglong2 x;
        x.x = sA[0]; x.y = sA[1]; p0[0] = x;
        x.x = sA[2]; x.y = sA[3]; p0[1] = x;
        x.x = sB[0]; x.y = sB[1]; p1[0] = x;
        x.x = sB[2]; x.y = sB[3]; p1[1] = x;
    }
}

extern "C" void kernel_launch(void* const* d_in, const int* in_sizes, int n_in,
                              void* d_out, int out_size) {
    int o = (n_in >= 8) ? 1 : 0;
    const float* r  = (const float*)d_in[o + 0];
    const float* w  = (const float*)d_in[o + 1];
    const float* k  = (const float*)d_in[o + 2];
    const float* v  = (const float*)d_in[o + 3];
    const float* a  = (const float*)d_in[o + 4];
    const float* b  = (const float*)d_in[o + 5];
    const float* s0 = (const float*)d_in[o + 6];

    float* y    = (float*)d_out;                  // x: [T, H, 1, N]
    float* sout = y + (size_t)TLEN * DIM;         // state2_out: [H, N, N]

    wkv7_kernel<<<128, 128>>>(r, w, k, v, a, b, s0, y, sout);
}

// round 13
// speedup vs baseline: 1.1489x; 1.1489x over previous
#include <cuda_runtime.h>
#include <cstdint>

#define TLEN 4096
#define NH 32
#define HS 64
#define DIM (NH*HS)
#define DEPTH 8
#define STRIDE 336   // floats/slot: w64|k64|a64|b64|r64|v16

// grid=128 (32 heads x 4 quarters of 16 rows), block = ONE warp (32 threads).
// Lane = (g = lane>>3 row-group, lane8 = j-slice); lane owns FOUR rows'
// 8-float j-slices (rows q*16+g*4..+3), state = 16 u64 f32x2 regs.
// MIO minimization: 11 LDS + 11 SHFL (reduce-scatter) + 3 cp.async + 1 STG
// per step. Per-warp cp.async ring DEPTH=8, 8x-unrolled, compile-time slots.

__device__ __forceinline__ uint32_t smem_u32(const void* p) {
    return (uint32_t)__cvta_generic_to_shared(p);
}

typedef unsigned long long u64;

#define MUL2(d,a,b)   asm("mul.rn.f32x2 %0, %1, %2;"     : "=l"(d) : "l"(a), "l"(b))
#define FMA2(d,a,b,c) asm("fma.rn.f32x2 %0, %1, %2, %3;" : "=l"(d) : "l"(a), "l"(b), "l"(c))
#define PACK2(d,lo,hi)   asm("mov.b64 %0, {%1, %2};" : "=l"(d) : "f"(lo), "f"(hi))
#define UNPACK2(lo,hi,v) asm("mov.b64 {%0, %1}, %2;" : "=f"(lo), "=f"(hi) : "l"(v))

#define DOT8(res, X, Y) do { \
    u64 _p; MUL2(_p, X[0], Y[0]); FMA2(_p, X[1], Y[1], _p); \
    FMA2(_p, X[2], Y[2], _p);     FMA2(_p, X[3], Y[3], _p); \
    float _lo, _hi; UNPACK2(_lo, _hi, _p); res = _lo + _hi; } while(0)

#define LD4x2(dst, ptr) do { \
    const ulonglong2* _p = (const ulonglong2*)(ptr); \
    ulonglong2 _x0 = _p[0], _x1 = _p[1]; \
    dst[0]=_x0.x; dst[1]=_x0.y; dst[2]=_x1.x; dst[3]=_x1.y; } while(0)

// Reduce-scatter 4 values over the 8-lane group (xor 4,2,1).
// Returns full sum of p_v where v = ((lane&4)>>1)|((lane&2)>>1).
__device__ __forceinline__ float scat4(float p0, float p1, float p2, float p3,
                                       bool bb4, bool bb2) {
    float s0 = bb4 ? p0 : p2, s1 = bb4 ? p1 : p3;
    float r0 = __shfl_xor_sync(0xffffffffu, s0, 4);
    float r1 = __shfl_xor_sync(0xffffffffu, s1, 4);
    float q0 = (bb4 ? p2 : p0) + r0;
    float q1 = (bb4 ? p3 : p1) + r1;
    float s  = bb2 ? q0 : q1;
    float r  = __shfl_xor_sync(0xffffffffu, s, 2);
    float k  = (bb2 ? q1 : q0) + r;
    k += __shfl_xor_sync(0xffffffffu, k, 1);
    return k;
}

// Allgather the 4 scattered values back to every lane of the group.
__device__ __forceinline__ void gath4(float m, bool bb4, bool bb2,
                                      float& a0, float& a1, float& a2, float& a3) {
    float n = __shfl_xor_sync(0xffffffffu, m, 2);
    float e = bb2 ? n : m;       // even index of my half
    float o = bb2 ? m : n;       // odd index of my half
    float c0 = __shfl_xor_sync(0xffffffffu, e, 4);
    float c1 = __shfl_xor_sync(0xffffffffu, o, 4);
    a0 = bb4 ? c0 : e; a1 = bb4 ? c1 : o;
    a2 = bb4 ? e : c0; a3 = bb4 ? o : c1;
}

__global__ void __launch_bounds__(32, 1) wkv7_kernel(
    const float* __restrict__ rr, const float* __restrict__ ww,
    const float* __restrict__ kk, const float* __restrict__ vv_,
    const float* __restrict__ aa, const float* __restrict__ bb,
    const float* __restrict__ s0, float* __restrict__ y, float* __restrict__ sout)
{
    const int blk   = blockIdx.x;
    const int h     = blk >> 2;
    const int q     = blk & 3;
    const int lane  = threadIdx.x;
    const int lane8 = lane & 7;
    const int g     = lane >> 3;
    const int j0    = lane8 * 8;
    const int hbase = h * HS;
    const int rowb  = q * 16 + g * 4;              // first of my 4 rows
    const bool bb4  = (lane & 4) != 0;
    const bool bb2  = (lane & 2) != 0;
    const int vmap  = ((lane & 4) >> 1) | ((lane & 2) >> 1);

    __shared__ __align__(16) float ring[DEPTH][STRIDE];

    // State: 4 rows x 8 floats (4 u64 each)
    u64 S0[4], S1[4], S2[4], S3[4];
    {
        const float* sp = s0 + ((size_t)h * HS + rowb) * HS + j0;
        LD4x2(S0, sp);
        LD4x2(S1, sp + HS);
        LD4x2(S2, sp + 2 * HS);
        LD4x2(S3, sp + 3 * HS);
    }

    // cp.async fill: chunks c = lane, lane+32, lane+64 (c<84), 16B each.
    const float* src0 = ((lane >> 4) ? kk : ww) + hbase + (lane & 15) * 4;
    const uint32_t od0 = lane * 4u;
    const float* src1 = ((lane >> 4) ? bb : aa) + hbase + (lane & 15) * 4;
    const uint32_t od1 = 128u + lane * 4u;
    const float* src2 = 0; uint32_t od2 = 0;
    if (lane < 16)      { src2 = rr  + hbase + lane * 4;               od2 = 256u + lane * 4u; }
    else if (lane < 20) { src2 = vv_ + hbase + q * 16 + (lane - 16) * 4; od2 = 320u + (lane - 16) * 4u; }

#define ISSUE(tt, ss) do { \
    size_t _off = (size_t)(tt) * DIM; \
    uint32_t _sb = smem_u32(&ring[ss][0]); \
    asm volatile("cp.async.cg.shared.global [%0], [%1], 16;" :: "r"(_sb + od0*4u), "l"(src0 + _off)); \
    asm volatile("cp.async.cg.shared.global [%0], [%1], 16;" :: "r"(_sb + od1*4u), "l"(src1 + _off)); \
    if (src2) asm volatile("cp.async.cg.shared.global [%0], [%1], 16;" :: "r"(_sb + od2*4u), "l"(src2 + _off)); \
    asm volatile("cp.async.commit_group;"); \
} while(0)

    #pragma unroll
    for (int i = 0; i < DEPTH; i++) ISSUE(i, i);

    // a_0 directly from gmem
    u64 a2[4];
    LD4x2(a2, aa + hbase + j0);

    float yp0 = 0.f, yp1 = 0.f, yp2 = 0.f, yp3 = 0.f;
    float* const ystore = y + hbase + rowb + vmap;   // this lane's y column

#define STEPBODY(T, SLOT, SLOTN) do { \
    const float* sl  = &ring[SLOT][0]; \
    const float* sln = &ring[SLOTN][0]; \
    /* sa dots from current state (a2 = a_T) */ \
    float p0, p1, p2, p3; \
    DOT8(p0, S0, a2); \
    DOT8(p1, S1, a2); \
    DOT8(p2, S2, a2); \
    DOT8(p3, S3, a2); \
    float sav = scat4(p0, p1, p2, p3, bb4, bb2); \
    /* deferred y_{T-1}: scatter + store (independent, fills shfl slack) */ \
    { \
        float yv = scat4(yp0, yp1, yp2, yp3, bb4, bb2); \
        int tprev = (T) - ((T) != 0); \
        if ((lane & 1) == 0) ystore[(size_t)tprev * DIM] = yv; \
    } \
    float sa0, sa1, sa2, sa3; \
    gath4(sav, bb4, bb2, sa0, sa1, sa2, sa3); \
    /* operands */ \
    u64 wv[4], kv[4], bv[4], rv[4]; \
    LD4x2(wv, sl + j0); \
    LD4x2(kv, sl + 64 + j0); \
    LD4x2(bv, sl + 192 + j0); \
    LD4x2(rv, sl + 256 + j0); \
    const float4 vq = *(const float4*)(sl + 320 + g * 4); \
    LD4x2(a2, sln + 128 + j0); \
    /* update 4 rows: s = s*w + v*k + sa*b */ \
    u64 v0b, v1b, v2b, v3b, c0b, c1b, c2b, c3b; \
    PACK2(v0b, vq.x, vq.x); PACK2(v1b, vq.y, vq.y); \
    PACK2(v2b, vq.z, vq.z); PACK2(v3b, vq.w, vq.w); \
    PACK2(c0b, sa0, sa0); PACK2(c1b, sa1, sa1); \
    PACK2(c2b, sa2, sa2); PACK2(c3b, sa3, sa3); \
    _Pragma("unroll") \
    for (int i = 0; i < 4; i++) { \
        u64 t0; MUL2(t0, S0[i], wv[i]); FMA2(t0, v0b, kv[i], t0); FMA2(S0[i], c0b, bv[i], t0); \
        u64 t1; MUL2(t1, S1[i], wv[i]); FMA2(t1, v1b, kv[i], t1); FMA2(S1[i], c1b, bv[i], t1); \
        u64 t2; MUL2(t2, S2[i], wv[i]); FMA2(t2, v2b, kv[i], t2); FMA2(S2[i], c2b, bv[i], t2); \
        u64 t3; MUL2(t3, S3[i], wv[i]); FMA2(t3, v3b, kv[i], t3); FMA2(S3[i], c3b, bv[i], t3); \
    } \
    /* y partials (reduced+stored next step) */ \
    DOT8(yp0, S0, rv); \
    DOT8(yp1, S1, rv); \
    DOT8(yp2, S2, rv); \
    DOT8(yp3, S3, rv); \
} while(0)

    for (int tb = 0; tb < TLEN - DEPTH; tb += DEPTH) {
        #pragma unroll
        for (int u = 0; u < DEPTH; u++) {
            const int t = tb + u;
            asm volatile("cp.async.wait_group 6;");
            __syncwarp();
            STEPBODY(t, u, (u + 1) & (DEPTH - 1));
            ISSUE(t + DEPTH, u);
        }
    }

    // Tail: everything staged.
    asm volatile("cp.async.wait_group 0;");
    __syncwarp();
    #pragma unroll
    for (int u = 0; u < DEPTH; u++) {
        const int t = TLEN - DEPTH + u;
        STEPBODY(t, u, (u + 1) & (DEPTH - 1));   // final a2 prefetch unused
    }

    // Epilogue: y_{TLEN-1}
    {
        float yv = scat4(yp0, yp1, yp2, yp3, bb4, bb2);
        if ((lane & 1) == 0) ystore[(size_t)(TLEN - 1) * DIM] = yv;
    }

    // Final state
    {
        float* sp = sout + ((size_t)h * HS + rowb) * HS + j0;
        ulonglong2 x;
        ulonglong2* p;
        p = (ulonglong2*)sp;
        x.x = S0[0]; x.y = S0[1]; p[0] = x;  x.x = S0[2]; x.y = S0[3]; p[1] = x;
        p = (ulonglong2*)(sp + HS);
        x.x = S1[0]; x.y = S1[1]; p[0] = x;  x.x = S1[2]; x.y = S1[3]; p[1] = x;
        p = (ulonglong2*)(sp + 2 * HS);
        x.x = S2[0]; x.y = S2[1]; p[0] = x;  x.x = S2[2]; x.y = S2[3]; p[1] = x;
        p = (ulonglong2*)(sp + 3 * HS);
        x.x = S3[0]; x.y = S3[1]; p[0] = x;  x.x = S3[2]; x.y = S3[3]; p[1] = x;
    }
}

extern "C" void kernel_launch(void* const* d_in, const int* in_sizes, int n_in,
                              void* d_out, int out_size) {
    int o = (n_in >= 8) ? 1 : 0;
    const float* r  = (const float*)d_in[o + 0];
    const float* w  = (const float*)d_in[o + 1];
    const float* k  = (const float*)d_in[o + 2];
    const float* v  = (const float*)d_in[o + 3];
    const float* a  = (const float*)d_in[o + 4];
    const float* b  = (const float*)d_in[o + 5];
    const float* s0 = (const float*)d_in[o + 6];

    float* y    = (float*)d_out;                  // x: [T, H, 1, N]
    float* sout = y + (size_t)TLEN * DIM;         // state2_out: [H, N, N]

    wkv7_kernel<<<128, 32>>>(r, w, k, v, a, b, s0, y, sout);
}